// round 14
// baseline (speedup 1.0000x reference)
#include <cuda_runtime.h>
#include <math.h>
#include <stdint.h>

#define DM    1024
#define DI    2048
#define HD    64
#define NH    32
#define DS    128
#define DCONV 4
#define CDIM  (DI + 2*DS)         // 2304
#define DIP   (2*DI + 2*DS + NH)  // 4384
#define DIPP  4480                // DIP padded to 128-multiple for GEMM1
#define BSZ   4
#define LSEQ  1024
#define TOK   (BSZ*LSEQ)          // 4096
#define EPSV  1e-5f
#define NCHK   4
#define LCHUNK 256                // scan chunk length
#define NBH    (BSZ*NH)           // 128

// ---------------- scratch (static device globals; no allocations) ----------
__device__ float g_h[(size_t)TOK*DM];
__device__ float g_zx[(size_t)TOK*DIPP];
__device__ float g_xc[2][(size_t)TOK*DI];
__device__ float g_Bc[2][(size_t)TOK*DS];
__device__ float g_Cc[2][(size_t)TOK*DS];
__device__ float g_dt[2][(size_t)TOK*NH];
__device__ float g_dA[2][(size_t)TOK*NH];
__device__ float g_y [2][(size_t)TOK*DI];
__device__ float g_comb[(size_t)TOK*DI];
__device__ float g_o[(size_t)TOK*DM];
__device__ int   g_pos[TOK];
__device__ float g_w1t[(size_t)DIPP*DM];
__device__ float g_w2t[(size_t)DM*DI];
__device__ float g_cp[2][(size_t)TOK*NH];
__device__ float g_E[(size_t)2*NBH*3*HD*DS];   // end states, chunks 0..2
__device__ float g_P[2][NBH][NCHK];            // per-chunk total decay

// ---------------- small asm helpers -----------------------------------------
__device__ __forceinline__ uint32_t smem_u32(const void* p) {
    uint32_t a;
    asm("{ .reg .u64 t; cvta.to.shared.u64 t, %1; cvt.u32.u64 %0, t; }" : "=r"(a) : "l"(p));
    return a;
}
__device__ __forceinline__ void cp16(uint32_t dst, const void* src) {
    asm volatile("cp.async.cg.shared.global [%0], [%1], 16;" :: "r"(dst), "l"(src) : "memory");
}
__device__ __forceinline__ void cp4(uint32_t dst, const void* src) {
    asm volatile("cp.async.ca.shared.global [%0], [%1], 4;" :: "r"(dst), "l"(src) : "memory");
}
#define CP_COMMIT() asm volatile("cp.async.commit_group;" ::: "memory")
#define CP_WAIT1()  asm volatile("cp.async.wait_group 1;" ::: "memory")
#define CP_WAIT0()  asm volatile("cp.async.wait_group 0;" ::: "memory")

__device__ __forceinline__ uint32_t sw128(uint32_t off) { return off ^ ((off >> 3) & 0x70); }

__device__ __forceinline__ float rna_tf32(float x) {
    uint32_t u;
    asm("cvt.rna.tf32.f32 %0, %1;" : "=r"(u) : "f"(x));
    return __uint_as_float(u);
}

__device__ __forceinline__ void ldsm4(uint32_t& r0, uint32_t& r1, uint32_t& r2, uint32_t& r3,
                                      uint32_t addr) {
    asm volatile("ldmatrix.sync.aligned.m8n8.x4.shared.b16 {%0,%1,%2,%3}, [%4];"
                 : "=r"(r0), "=r"(r1), "=r"(r2), "=r"(r3) : "r"(addr));
}

// ---------------- f32x2 helpers ---------------------------------------------
typedef unsigned long long ull;
__device__ __forceinline__ ull pack2(float a, float b) {
    ull r; asm("mov.b64 %0, {%1,%2};" : "=l"(r) : "f"(a), "f"(b)); return r;
}
__device__ __forceinline__ void unpack2(float& a, float& b, ull v) {
    asm("mov.b64 {%0,%1}, %2;" : "=f"(a), "=f"(b) : "l"(v));
}
__device__ __forceinline__ ull mul2(ull a, ull b) {
    ull r; asm("mul.rn.f32x2 %0, %1, %2;" : "=l"(r) : "l"(a), "l"(b)); return r;
}
__device__ __forceinline__ void fma2(ull& d, ull a, ull b, ull c) {
    asm("fma.rn.f32x2 %0, %1, %2, %3;" : "=l"(d) : "l"(a), "l"(b), "l"(c));
}

// ---------------- generic helpers -------------------------------------------
__device__ __forceinline__ float block_sum(float v) {
    __shared__ float sh[33];
    int lane = threadIdx.x & 31, w = threadIdx.x >> 5;
    #pragma unroll
    for (int o = 16; o > 0; o >>= 1) v += __shfl_xor_sync(0xffffffffu, v, o);
    if (lane == 0) sh[w] = v;
    __syncthreads();
    if (threadIdx.x == 0) {
        float t = 0.f;
        int nw = blockDim.x >> 5;
        for (int i = 0; i < nw; i++) t += sh[i];
        sh[32] = t;
    }
    __syncthreads();
    float r = sh[32];
    __syncthreads();
    return r;
}
__device__ __forceinline__ float siluf(float x) { return x / (1.f + expf(-x)); }

// ---------------- fused pre-kernel: prep_w1 | pos | ln_in ---------------------
#define W1B 4480
#define W2B 2048
__global__ void __launch_bounds__(256) fused_pre_kernel(const float* __restrict__ in,
                                                        const unsigned char* __restrict__ mask,
                                                        const float* __restrict__ w1) {
    int bx = blockIdx.x;
    if (bx < W1B) {
        int i4 = bx * 256 + threadIdx.x;
        int row = i4 >> 8;
        float4 v = make_float4(0.f, 0.f, 0.f, 0.f);
        if (row < DIP) {
            float4 s = ((const float4*)w1)[i4];
            v = make_float4(rna_tf32(s.x), rna_tf32(s.y), rna_tf32(s.z), rna_tf32(s.w));
        }
        ((float4*)g_w1t)[i4] = v;
    } else if (bx < W1B + BSZ) {
        int b = bx - W1B;
        float cnt = 0.f;
        for (int i = threadIdx.x; i < LSEQ; i += 256)
            cnt += (mask[b*LSEQ + i] == 0) ? 1.f : 0.f;
        float total = block_sum(cnt);
        int len = (int)(total + 0.5f);
        for (int i = threadIdx.x; i < LSEQ; i += 256)
            g_pos[b*LSEQ + i] = (i < len) ? (len - 1 - i) : i;
    } else {
        int row = bx - (W1B + BSZ);
        const float* x = in + (size_t)row * DM;
        float s = 0.f, s2 = 0.f;
        for (int i = threadIdx.x; i < DM; i += 256) { float v = x[i]; s += v; s2 += v*v; }
        float sum = block_sum(s), sums = block_sum(s2);
        float mu = sum / DM, var = sums / DM - mu*mu;
        float rs = rsqrtf(var + EPSV);
        float* o = g_h + (size_t)row * DM;
        for (int i = threadIdx.x; i < DM; i += 256)
            o[i] = rna_tf32((x[i] - mu) * rs);
    }
}

__global__ void __launch_bounds__(256) prep_w2_kernel(const float* __restrict__ w2) {
    int i4 = blockIdx.x * 256 + threadIdx.x;
    float4 s = ((const float4*)w2)[i4];
    ((float4*)g_w2t)[i4] = make_float4(rna_tf32(s.x), rna_tf32(s.y),
                                       rna_tf32(s.z), rna_tf32(s.w));
}

__global__ void ln_out_kernel(float* __restrict__ out) {
    int row = blockIdx.x;
    const float* x = g_o + (size_t)row * DM;
    float s = 0.f, s2 = 0.f;
    for (int i = threadIdx.x; i < DM; i += blockDim.x) { float v = x[i]; s += v; s2 += v*v; }
    float sum = block_sum(s), sums = block_sum(s2);
    float mu = sum / DM, var = sums / DM - mu*mu;
    float rs = rsqrtf(var + EPSV);
    float* o = out + (size_t)row * DM;
    for (int i = threadIdx.x; i < DM; i += blockDim.x) o[i] = (x[i] - mu) * rs;
}

// ---------------- tf32 mma.sync GEMM (NT), 3 stages -> 2 CTAs/SM -------------
#define GST 3
#define STG_BYTES 32768
#define GEMM_SMEM (GST*STG_BYTES + 1024)

__device__ __forceinline__ void mma_gemm_body(const float* __restrict__ A,
                                              const float* __restrict__ B,
                                              float* __restrict__ C,
                                              int N, int K) {
    extern __shared__ char dynsmem[];
    uint32_t sbase = (smem_u32(dynsmem) + 1023) & ~1023u;

    const int tid  = threadIdx.x;
    const int warp = tid >> 5, lane = tid & 31;
    const int m0 = blockIdx.y * 128, n0 = blockIdx.x * 128;
    const int wm = (warp & 1) * 64, wn = (warp >> 1) * 32;
    const int NITER = K >> 5;

    const int lrow = tid >> 3, lc4 = tid & 7;
    uint32_t dst_off[4];
    const float* aptr[4];
    const float* bptr[4];
    #pragma unroll
    for (int i = 0; i < 4; i++) {
        int r = lrow + i * 32;
        dst_off[i] = sw128((uint32_t)(r * 128 + lc4 * 16));
        aptr[i] = A + (size_t)(m0 + r) * K + lc4 * 4;
        bptr[i] = B + (size_t)(n0 + r) * K + lc4 * 4;
    }

    auto issue = [&](int kc, int st) {
        uint32_t sa = sbase + st * STG_BYTES;
        uint32_t sb = sa + 16384;
        int koff = kc * 32;
        #pragma unroll
        for (int i = 0; i < 4; i++) {
            cp16(sa + dst_off[i], aptr[i] + koff);
            cp16(sb + dst_off[i], bptr[i] + koff);
        }
        CP_COMMIT();
    };

    float acc[4][4][4];
    #pragma unroll
    for (int i = 0; i < 4; i++)
        #pragma unroll
        for (int j = 0; j < 4; j++)
            #pragma unroll
            for (int k = 0; k < 4; k++) acc[i][j][k] = 0.f;

    issue(0, 0); issue(1, 1);

    const int mq   = lane >> 3;
    const int arow = (lane & 7) + ((mq & 1) << 3);
    const int aoff = (mq & 2) ? 16 : 0;
    const int brow = (lane & 7) + ((mq & 2) << 2);
    const int boff = (mq & 1) * 16;
    int arbase[4], arx[4];
    #pragma unroll
    for (int mt = 0; mt < 4; mt++) {
        int r = wm + mt*16 + arow;
        arbase[mt] = r * 128; arx[mt] = (r & 7) << 4;
    }
    int brbase[2], brx[2];
    #pragma unroll
    for (int np = 0; np < 2; np++) {
        int r = wn + np*16 + brow;
        brbase[np] = r * 128; brx[np] = (r & 7) << 4;
    }

    int rstage = 0, wstage = 2;
    for (int kc = 0; kc < NITER; kc++) {
        CP_WAIT1();
        __syncthreads();
        if (kc + 2 < NITER) issue(kc + 2, wstage);
        else CP_COMMIT();

        uint32_t sa = sbase + rstage * STG_BYTES;
        uint32_t sb = sa + 16384;
        rstage = (rstage == GST-1) ? 0 : rstage + 1;
        wstage = (wstage == GST-1) ? 0 : wstage + 1;

        #pragma unroll
        for (int ks = 0; ks < 4; ks++) {
            int kb = ks * 32;
            uint32_t af[4][4];
            #pragma unroll
            for (int mt = 0; mt < 4; mt++) {
                uint32_t addr = sa + arbase[mt] + (uint32_t)((kb + aoff) ^ arx[mt]);
                ldsm4(af[mt][0], af[mt][1], af[mt][2], af[mt][3], addr);
            }
            uint32_t bf[4][2];
            #pragma unroll
            for (int np = 0; np < 2; np++) {
                uint32_t addr = sb + brbase[np] + (uint32_t)((kb + boff) ^ brx[np]);
                ldsm4(bf[2*np][0], bf[2*np][1], bf[2*np+1][0], bf[2*np+1][1], addr);
            }
            #pragma unroll
            for (int mt = 0; mt < 4; mt++)
                #pragma unroll
                for (int nt = 0; nt < 4; nt++) {
                    asm volatile(
                        "mma.sync.aligned.m16n8k8.row.col.f32.tf32.tf32.f32 "
                        "{%0,%1,%2,%3}, {%4,%5,%6,%7}, {%8,%9}, {%0,%1,%2,%3};"
                        : "+f"(acc[mt][nt][0]), "+f"(acc[mt][nt][1]),
                          "+f"(acc[mt][nt][2]), "+f"(acc[mt][nt][3])
                        : "r"(af[mt][0]), "r"(af[mt][1]), "r"(af[mt][2]), "r"(af[mt][3]),
                          "r"(bf[nt][0]), "r"(bf[nt][1]));
                }
        }
    }

    #pragma unroll
    for (int mt = 0; mt < 4; mt++) {
        #pragma unroll
        for (int nt = 0; nt < 4; nt++) {
            int r = m0 + wm + mt*16 + (lane >> 2);
            int c = n0 + wn + nt*8 + 2*(lane & 3);
            *(float2*)&C[(size_t)r * N + c]       = make_float2(acc[mt][nt][0], acc[mt][nt][1]);
            *(float2*)&C[(size_t)(r + 8) * N + c] = make_float2(acc[mt][nt][2], acc[mt][nt][3]);
        }
    }
}

__global__ void __launch_bounds__(256, 2) mma_gemm1_kernel() {
    mma_gemm_body(g_h, g_w1t, g_zx, DIPP, DM);
}
__global__ void __launch_bounds__(256, 2) mma_gemm2_kernel() {
    mma_gemm_body(g_comb, g_w2t, g_o, DM, DI);
}

// ---------------- causal depthwise conv + silu + split + dt/dA ---------------
__global__ void conv_kernel(const float* __restrict__ cw_f, const float* __restrict__ cb_f,
                            const float* __restrict__ cw_r, const float* __restrict__ cb_r,
                            const float* __restrict__ dtb_f, const float* __restrict__ Al_f,
                            const float* __restrict__ dtb_r, const float* __restrict__ Al_r) {
    int t   = blockIdx.x;
    int dir = blockIdx.y;
    int b = t / LSEQ, lp = t % LSEQ;
    const float4* cw4 = (const float4*)(dir ? cw_r : cw_f);
    const float4* cb4 = (const float4*)(dir ? cb_r : cb_f);

    int rows[4];
    #pragma unroll
    for (int k = 0; k < 4; k++) {
        int j = lp + k - 3;
        rows[k] = (j >= 0) ? (b*LSEQ + (dir ? g_pos[b*LSEQ + j] : j)) : -1;
    }

    for (int c4 = threadIdx.x; c4 < CDIM/4; c4 += blockDim.x) {
        float4 bias = cb4[c4];
        float acc[4] = {bias.x, bias.y, bias.z, bias.w};
        float4 w[4];
        #pragma unroll
        for (int j = 0; j < 4; j++) w[j] = cw4[c4*4 + j];
        #pragma unroll
        for (int k = 0; k < 4; k++) {
            if (rows[k] >= 0) {
                float4 xv = *(const float4*)(g_zx + (size_t)rows[k]*DIPP + DI + c4*4);
                acc[0] = fmaf(((const float*)&w[0])[k], xv.x, acc[0]);
                acc[1] = fmaf(((const float*)&w[1])[k], xv.y, acc[1]);
                acc[2] = fmaf(((const float*)&w[2])[k], xv.z, acc[2]);
                acc[3] = fmaf(((const float*)&w[3])[k], xv.w, acc[3]);
            }
        }
        float4 v = make_float4(siluf(acc[0]), siluf(acc[1]), siluf(acc[2]), siluf(acc[3]));
        if (c4 < DI/4)                ((float4*)(g_xc[dir] + (size_t)t*DI))[c4] = v;
        else if (c4 < (DI+DS)/4)      ((float4*)(g_Bc[dir] + (size_t)t*DS))[c4 - DI/4] = v;
        else                          ((float4*)(g_Cc[dir] + (size_t)t*DS))[c4 - (DI+DS)/4] = v;
    }

    if (threadIdx.x < NH) {
        int hh = threadIdx.x;
        int srow = b*LSEQ + (dir ? g_pos[t] : lp);
        float dtr = g_zx[(size_t)srow*DIPP + DI + CDIM + hh] + (dir ? dtb_r : dtb_f)[hh];
        float dtv = (dtr > 20.f) ? dtr : log1pf(expf(dtr));
        float A = -expf((dir ? Al_r : Al_f)[hh]);
        g_dt[dir][(size_t)t*NH + hh] = dtv;
        g_dA[dir][(size_t)t*NH + hh] = expf(dtv * A);
    }
}

// ---------------- selective scan pass 1 (NCHK=4 chunks, double-buffered) ------
#define CH 16
#define NT (LCHUNK/CH)     // 16 tiles
__global__ void __launch_bounds__(128, 4) scan1_kernel(const float* __restrict__ Df,
                                                       const float* __restrict__ Dr) {
    int bid = blockIdx.x;
    int dir = bid & 1, ck = (bid >> 1) & 3, bh = bid >> 3;
    int b = bh / NH, hd = bh % NH;
    int tid = threadIdx.x;
    int lane = tid & 31, wd = tid >> 5;
    int nid = lane & 7, pg = lane >> 3;
    int p_base = wd*16 + pg*4;
    int n4 = nid*4;
    float Dv = (dir ? Dr : Df)[hd];
    const int t0 = ck * LCHUNK;

    __shared__ float sB[2][CH][DS], sC[2][CH][DS], sx[2][CH][HD];
    __shared__ float sdtf[2][CH], sdAf[2][CH];

    ull h2[4][8];
    #pragma unroll
    for (int p = 0; p < 4; p++)
        #pragma unroll
        for (int j = 0; j < 8; j++) h2[p][j] = 0ull;
    float cp = 1.f;

    const float* Bg  = g_Bc[dir] + (size_t)b*LSEQ*DS;
    const float* Cg  = g_Cc[dir] + (size_t)b*LSEQ*DS;
    const float* xg  = g_xc[dir] + (size_t)b*LSEQ*DI + (size_t)hd*HD;
    const float* dtg = g_dt[dir] + (size_t)b*LSEQ*NH + hd;
    const float* dAg = g_dA[dir] + (size_t)b*LSEQ*NH + hd;
    float* yg  = g_y[dir]  + (size_t)b*LSEQ*DI + (size_t)hd*HD;
    float* cpg = g_cp[dir] + (size_t)b*LSEQ*NH + hd;

    auto fill = [&](int tile, int buf) {
        int l0 = t0 + tile*CH;
        #pragma unroll
        for (int r = 0; r < 4; r++) {
            int e = r*128 + tid;
            int s = e >> 5, n = (e & 31) * 4;
            cp16(smem_u32(&sB[buf][s][n]), &Bg[(size_t)(l0+s)*DS + n]);
            cp16(smem_u32(&sC[buf][s][n]), &Cg[(size_t)(l0+s)*DS + n]);
        }
        #pragma unroll
        for (int r = 0; r < 2; r++) {
            int e = r*128 + tid;
            int s = e >> 4, p = (e & 15) * 4;
            cp16(smem_u32(&sx[buf][s][p]), &xg[(size_t)(l0+s)*DI + p]);
        }
        if (tid < CH) {
            cp4(smem_u32(&sdtf[buf][tid]), &dtg[(size_t)(l0+tid)*NH]);
            cp4(smem_u32(&sdAf[buf][tid]), &dAg[(size_t)(l0+tid)*NH]);
        }
        CP_COMMIT();
    };

    fill(0, 0);

    for (int tile = 0; tile < NT; tile++) {
        CP_WAIT0();
        __syncthreads();
        if (tile + 1 < NT) fill(tile + 1, (tile + 1) & 1);
        int buf = tile & 1;
        int l0 = t0 + tile*CH;

        #pragma unroll
        for (int s = 0; s < CH; s++) {
            float dt = sdtf[buf][s];
            float da = sdAf[buf][s];
            ull dA2 = pack2(da, da);
            float4 xv = *(const float4*)&sx[buf][s][p_base];
            ull kf2[4];
            {
                float k0 = dt*xv.x, k1 = dt*xv.y, k2 = dt*xv.z, k3 = dt*xv.w;
                kf2[0] = pack2(k0, k0); kf2[1] = pack2(k1, k1);
                kf2[2] = pack2(k2, k2); kf2[3] = pack2(k3, k3);
            }

            ull y2[4] = {0ull, 0ull, 0ull, 0ull};
            #pragma unroll
            for (int q = 0; q < 4; q++) {
                ulonglong2 bq = *(const ulonglong2*)&sB[buf][s][n4 + 32*q];
                ulonglong2 cq = *(const ulonglong2*)&sC[buf][s][n4 + 32*q];
                #pragma unroll
                for (int p = 0; p < 4; p++) {
                    ull t0v = mul2(h2[p][2*q], dA2);
                    fma2(h2[p][2*q], bq.x, kf2[p], t0v);
                    fma2(y2[p], h2[p][2*q], cq.x, y2[p]);
                    ull t1v = mul2(h2[p][2*q+1], dA2);
                    fma2(h2[p][2*q+1], bq.y, kf2[p], t1v);
                    fma2(y2[p], h2[p][2*q+1], cq.y, y2[p]);
                }
            }

            cp *= da;
            if (ck && tid == 0)
                cpg[(size_t)(l0+s)*NH] = cp;

            float yout[4];
            #pragma unroll
            for (int p = 0; p < 4; p++) {
                float a, c; unpack2(a, c, y2[p]);
                float yp = a + c;
                yp += __shfl_xor_sync(0xffffffffu, yp, 1);
                yp += __shfl_xor_sync(0xffffffffu, yp, 2);
                yp += __shfl_xor_sync(0xffffffffu, yp, 4);
                yout[p] = fmaf(Dv, ((const float*)&xv)[p], yp);
            }
            if (nid == 0)
                *(float4*)&yg[(size_t)(l0+s)*DI + p_base] =
                    make_float4(yout[0], yout[1], yout[2], yout[3]);
        }
    }

    if (tid == 0) g_P[dir][bh][ck] = cp;

    if (ck < 3) {   // emit end state
        float* E = g_E + ((size_t)((dir*NBH + bh)*3 + ck)) * (HD*DS);
        #pragma unroll
        for (int p = 0; p < 4; p++) {
            #pragma unroll
            for (int q = 0; q < 4; q++) {
                float a0, b0, a1, b1;
                unpack2(a0, b0, h2[p][2*q]);
                unpack2(a1, b1, h2[p][2*q+1]);
                *(float4*)&E[(size_t)(p_base+p)*DS + n4 + 32*q] =
                    make_float4(a0, b0, a1, b1);
            }
        }
    }
}

// ---------------- selective scan pass 3 (chunks 1..3 correction) --------------
__global__ void __launch_bounds__(128) scan3_kernel() {
    int bid = blockIdx.x;
    int dir = bid & 1;
    int r3  = bid >> 1;
    int ck  = (r3 % 3) + 1;
    int bh  = r3 / 3;
    int b = bh / NH, hd = bh % NH;
    int tid = threadIdx.x;
    int lane = tid & 31, wd = tid >> 5;
    int nid = lane & 7, pg = lane >> 3;
    int p_base = wd*16 + pg*4;
    int n4 = nid*4;

    ull e2[4][8];
    #pragma unroll
    for (int p = 0; p < 4; p++)
        #pragma unroll
        for (int q = 0; q < 8; q++) e2[p][q] = 0ull;
    float coeff = 1.f;
    for (int j = ck - 1; j >= 0; j--) {
        const float* E = g_E + ((size_t)((dir*NBH + bh)*3 + j)) * (HD*DS);
        ull c2 = pack2(coeff, coeff);
        #pragma unroll
        for (int p = 0; p < 4; p++) {
            #pragma unroll
            for (int q = 0; q < 4; q++) {
                float4 v = *(const float4*)&E[(size_t)(p_base+p)*DS + n4 + 32*q];
                fma2(e2[p][2*q],   pack2(v.x, v.y), c2, e2[p][2*q]);
                fma2(e2[p][2*q+1], pack2(v.z, v.w), c2, e2[p][2*q+1]);
            }
        }
        coeff *= g_P[dir][bh][j];
    }

    __shared__ float sC[CH][DS];
    __shared__ float scp[CH];

    const float* Cg  = g_Cc[dir] + (size_t)b*LSEQ*DS;
    const float* cpg = g_cp[dir] + (size_t)b*LSEQ*NH + hd;
    float* yg = g_y[dir] + (size_t)b*LSEQ*DI + (size_t)hd*HD;

    const int tstart = ck * LCHUNK;
    for (int l0 = tstart; l0 < tstart + LCHUNK; l0 += CH) {
        #pragma unroll
        for (int r = 0; r < 4; r++) {
            int e = r*128 + tid;
            int s = e >> 5, n = (e & 31) * 4;
            *(float4*)&sC[s][n] = *(const float4*)&Cg[(size_t)(l0+s)*DS + n];
        }
        if (tid < CH)
            scp[tid] = cpg[(size_t)(l0+tid)*NH];
        __syncthreads();

        #pragma unroll
        for (int s = 0; s < CH; s++) {
            ull y2[4] = {0ull, 0ull, 0ull, 0ull};
            #pragma unroll
            for (int q = 0; q < 4; q++) {
                ulonglong2 cq = *(const ulonglong2*)&sC[s][n4 + 32*q];
                #pragma unroll
                for (int p = 0; p < 4; p++) {
                    fma2(y2[p], e2[p][2*q],   cq.x, y2[p]);
                    fma2(y2[p], e2[p][2*q+1], cq.y, y2[p]);
                }
            }
            float cp = scp[s];
            float yout[4];
            #pragma unroll
            for (int p = 0; p < 4; p++) {
                float a, c; unpack2(a, c, y2[p]);
                float yp = a + c;
                yp += __shfl_xor_sync(0xffffffffu, yp, 1);
                yp += __shfl_xor_sync(0xffffffffu, yp, 2);
                yp += __shfl_xor_sync(0xffffffffu, yp, 4);
                yout[p] = cp * yp;
            }
            if (nid == 0) {
                float4 old = *(float4*)&yg[(size_t)(l0+s)*DI + p_base];
                old.x += yout[0]; old.y += yout[1];
                old.z += yout[2]; old.w += yout[3];
                *(float4*)&yg[(size_t)(l0+s)*DI + p_base] = old;
            }
        }
        __syncthreads();
    }
}

// ---------------- gating + RMSNorm (in place on g_y) --------------------------
__global__ void gate_kernel(const float* __restrict__ nwf, const float* __restrict__ nwr) {
    int t = blockIdx.x, dir = blockIdx.y;
    int b = t / LSEQ, lp = t % LSEQ;
    int ztok = b*LSEQ + (dir ? g_pos[t] : lp);
    const float* nw = dir ? nwr : nwf;
    float* y = g_y[dir] + (size_t)t*DI;
    const float* z = g_zx + (size_t)ztok*DIPP;

    float gv[8];
    float s2 = 0.f;
    #pragma unroll
    for (int r = 0; r < 8; r++) {
        int c = r*256 + threadIdx.x;
        float zv = z[c];
        float g = y[c] * siluf(zv);
        gv[r] = g;
        s2 = fmaf(g, g, s2);
    }
    float total = block_sum(s2);
    float sc = rsqrtf(total / DI + EPSV);
    #pragma unroll
    for (int r = 0; r < 8; r++) {
        int c = r*256 + threadIdx.x;
        y[c] = gv[r] * sc * nw[c];
    }
}

// ---------------- combine forward + flipped reverse (tf32-rounded) ------------
__global__ void combine_kernel() {
    int t = blockIdx.x;
    int b = t / LSEQ;
    int rt = b*LSEQ + g_pos[t];
    const float* yf = g_y[0] + (size_t)t*DI;
    const float* yr = g_y[1] + (size_t)rt*DI;
    float* o = g_comb + (size_t)t*DI;
    for (int c = threadIdx.x; c < DI; c += blockDim.x)
        o[c] = rna_tf32(0.5f * (yf[c] + yr[c]));
}

// ---------------- launch -------------------------------------------------------
extern "C" void kernel_launch(void* const* d_in, const int* in_sizes, int n_in,
                              void* d_out, int out_size) {
    const float* hidden  = (const float*)d_in[0];
    const unsigned char* mask = (const unsigned char*)d_in[1];
    const float* in_proj = (const float*)d_in[2];
    const float* out_proj= (const float*)d_in[3];
    const float* cw_f  = (const float*)d_in[4];
    const float* cb_f  = (const float*)d_in[5];
    const float* dtb_f = (const float*)d_in[6];
    const float* Al_f  = (const float*)d_in[7];
    const float* D_f   = (const float*)d_in[8];
    const float* nw_f  = (const float*)d_in[9];
    const float* cw_r  = (const float*)d_in[10];
    const float* cb_r  = (const float*)d_in[11];
    const float* dtb_r = (const float*)d_in[12];
    const float* Al_r  = (const float*)d_in[13];
    const float* D_r   = (const float*)d_in[14];
    const float* nw_r  = (const float*)d_in[15];
    float* out = (float*)d_out;

    cudaFuncSetAttribute(mma_gemm1_kernel, cudaFuncAttributeMaxDynamicSharedMemorySize, GEMM_SMEM);
    cudaFuncSetAttribute(mma_gemm2_kernel, cudaFuncAttributeMaxDynamicSharedMemorySize, GEMM_SMEM);

    // scan1 at launch index 3 for ncu capture
    fused_pre_kernel<<<W1B + BSZ + TOK, 256>>>(hidden, mask, in_proj);
    mma_gemm1_kernel<<<dim3(DIPP/128, TOK/128), 256, GEMM_SMEM>>>();
    conv_kernel<<<dim3(TOK, 2), 256>>>(cw_f, cb_f, cw_r, cb_r, dtb_f, Al_f, dtb_r, Al_r);
    scan1_kernel<<<NBH*NCHK*2, 128>>>(D_f, D_r);
    scan3_kernel<<<NBH*3*2, 128>>>();
    gate_kernel<<<dim3(TOK, 2), 256>>>(nw_f, nw_r);
    combine_kernel<<<TOK, 256>>>();
    prep_w2_kernel<<<W2B, 256>>>(out_proj);
    mma_gemm2_kernel<<<dim3(DM/128, TOK/128), 256, GEMM_SMEM>>>();
    ln_out_kernel<<<TOK, 256>>>(out);
}

// round 15
// speedup vs baseline: 1.1425x; 1.1425x over previous
#include <cuda_runtime.h>
#include <math.h>
#include <stdint.h>

#define DM    1024
#define DI    2048
#define HD    64
#define NH    32
#define DS    128
#define DCONV 4
#define CDIM  (DI + 2*DS)         // 2304
#define DIP   (2*DI + 2*DS + NH)  // 4384
#define DIPP  4480                // DIP padded to 128-multiple for GEMM1
#define BSZ   4
#define LSEQ  1024
#define TOK   (BSZ*LSEQ)          // 4096
#define EPSV  1e-5f
#define LCHUNK 512                // scan chunk length (NCHUNK=2)

// ---------------- scratch (static device globals; no allocations) ----------
__device__ float g_h[(size_t)TOK*DM];
__device__ float g_zx[(size_t)TOK*DIPP];
__device__ float g_xc[2][(size_t)TOK*DI];
__device__ float g_Bc[2][(size_t)TOK*DS];
__device__ float g_Cc[2][(size_t)TOK*DS];
__device__ float g_dt[2][(size_t)TOK*NH];
__device__ float g_dA[2][(size_t)TOK*NH];
__device__ float g_y [2][(size_t)TOK*DI];
__device__ float g_comb[(size_t)TOK*DI];
__device__ float g_o[(size_t)TOK*DM];
__device__ int   g_pos[TOK];
__device__ float g_w1t[(size_t)DIPP*DM];
__device__ float g_w2t[(size_t)DM*DI];
__device__ float g_cp[2][(size_t)TOK*NH];
__device__ float g_E[(size_t)2*BSZ*NH*HD*DS];

// ---------------- small asm helpers -----------------------------------------
__device__ __forceinline__ uint32_t smem_u32(const void* p) {
    uint32_t a;
    asm("{ .reg .u64 t; cvta.to.shared.u64 t, %1; cvt.u32.u64 %0, t; }" : "=r"(a) : "l"(p));
    return a;
}
__device__ __forceinline__ void cp16(uint32_t dst, const void* src) {
    asm volatile("cp.async.cg.shared.global [%0], [%1], 16;" :: "r"(dst), "l"(src) : "memory");
}
__device__ __forceinline__ void cp4(uint32_t dst, const void* src) {
    asm volatile("cp.async.ca.shared.global [%0], [%1], 4;" :: "r"(dst), "l"(src) : "memory");
}
#define CP_COMMIT() asm volatile("cp.async.commit_group;" ::: "memory")
#define CP_WAIT1()  asm volatile("cp.async.wait_group 1;" ::: "memory")
#define CP_WAIT0()  asm volatile("cp.async.wait_group 0;" ::: "memory")

__device__ __forceinline__ uint32_t sw128(uint32_t off) { return off ^ ((off >> 3) & 0x70); }

__device__ __forceinline__ float rna_tf32(float x) {
    uint32_t u;
    asm("cvt.rna.tf32.f32 %0, %1;" : "=r"(u) : "f"(x));
    return __uint_as_float(u);
}

__device__ __forceinline__ void ldsm4(uint32_t& r0, uint32_t& r1, uint32_t& r2, uint32_t& r3,
                                      uint32_t addr) {
    asm volatile("ldmatrix.sync.aligned.m8n8.x4.shared.b16 {%0,%1,%2,%3}, [%4];"
                 : "=r"(r0), "=r"(r1), "=r"(r2), "=r"(r3) : "r"(addr));
}

// ---------------- f32x2 helpers ---------------------------------------------
typedef unsigned long long ull;
__device__ __forceinline__ ull pack2(float a, float b) {
    ull r; asm("mov.b64 %0, {%1,%2};" : "=l"(r) : "f"(a), "f"(b)); return r;
}
__device__ __forceinline__ void unpack2(float& a, float& b, ull v) {
    asm("mov.b64 {%0,%1}, %2;" : "=f"(a), "=f"(b) : "l"(v));
}
__device__ __forceinline__ ull mul2(ull a, ull b) {
    ull r; asm("mul.rn.f32x2 %0, %1, %2;" : "=l"(r) : "l"(a), "l"(b)); return r;
}
__device__ __forceinline__ void fma2(ull& d, ull a, ull b, ull c) {
    asm("fma.rn.f32x2 %0, %1, %2, %3;" : "=l"(d) : "l"(a), "l"(b), "l"(c));
}

// ---------------- generic helpers -------------------------------------------
__device__ __forceinline__ float block_sum(float v) {
    __shared__ float sh[33];
    int lane = threadIdx.x & 31, w = threadIdx.x >> 5;
    #pragma unroll
    for (int o = 16; o > 0; o >>= 1) v += __shfl_xor_sync(0xffffffffu, v, o);
    if (lane == 0) sh[w] = v;
    __syncthreads();
    if (threadIdx.x == 0) {
        float t = 0.f;
        int nw = blockDim.x >> 5;
        for (int i = 0; i < nw; i++) t += sh[i];
        sh[32] = t;
    }
    __syncthreads();
    float r = sh[32];
    __syncthreads();
    return r;
}
__device__ __forceinline__ float siluf(float x) { return x / (1.f + expf(-x)); }

// ---------------- fused pre-kernel: prep_w1 | pos | ln_in ---------------------
#define W1B 4480
#define W2B 2048
__global__ void __launch_bounds__(256) fused_pre_kernel(const float* __restrict__ in,
                                                        const unsigned char* __restrict__ mask,
                                                        const float* __restrict__ w1) {
    int bx = blockIdx.x;
    if (bx < W1B) {
        int i4 = bx * 256 + threadIdx.x;
        int row = i4 >> 8;
        float4 v = make_float4(0.f, 0.f, 0.f, 0.f);
        if (row < DIP) {
            float4 s = ((const float4*)w1)[i4];
            v = make_float4(rna_tf32(s.x), rna_tf32(s.y), rna_tf32(s.z), rna_tf32(s.w));
        }
        ((float4*)g_w1t)[i4] = v;
    } else if (bx < W1B + BSZ) {
        int b = bx - W1B;
        float cnt = 0.f;
        for (int i = threadIdx.x; i < LSEQ; i += 256)
            cnt += (mask[b*LSEQ + i] == 0) ? 1.f : 0.f;
        float total = block_sum(cnt);
        int len = (int)(total + 0.5f);
        for (int i = threadIdx.x; i < LSEQ; i += 256)
            g_pos[b*LSEQ + i] = (i < len) ? (len - 1 - i) : i;
    } else {
        int row = bx - (W1B + BSZ);
        const float* x = in + (size_t)row * DM;
        float s = 0.f, s2 = 0.f;
        for (int i = threadIdx.x; i < DM; i += 256) { float v = x[i]; s += v; s2 += v*v; }
        float sum = block_sum(s), sums = block_sum(s2);
        float mu = sum / DM, var = sums / DM - mu*mu;
        float rs = rsqrtf(var + EPSV);
        float* o = g_h + (size_t)row * DM;
        for (int i = threadIdx.x; i < DM; i += 256)
            o[i] = rna_tf32((x[i] - mu) * rs);
    }
}

__global__ void __launch_bounds__(256) prep_w2_kernel(const float* __restrict__ w2) {
    int i4 = blockIdx.x * 256 + threadIdx.x;
    float4 s = ((const float4*)w2)[i4];
    ((float4*)g_w2t)[i4] = make_float4(rna_tf32(s.x), rna_tf32(s.y),
                                       rna_tf32(s.z), rna_tf32(s.w));
}

__global__ void ln_out_kernel(float* __restrict__ out) {
    int row = blockIdx.x;
    const float* x = g_o + (size_t)row * DM;
    float s = 0.f, s2 = 0.f;
    for (int i = threadIdx.x; i < DM; i += blockDim.x) { float v = x[i]; s += v; s2 += v*v; }
    float sum = block_sum(s), sums = block_sum(s2);
    float mu = sum / DM, var = sums / DM - mu*mu;
    float rs = rsqrtf(var + EPSV);
    float* o = out + (size_t)row * DM;
    for (int i = threadIdx.x; i < DM; i += blockDim.x) o[i] = (x[i] - mu) * rs;
}

// ---------------- tf32 mma.sync GEMM (NT), 3 stages -> 2 CTAs/SM -------------
#define GST 3
#define STG_BYTES 32768
#define GEMM_SMEM (GST*STG_BYTES + 1024)

__device__ __forceinline__ void mma_gemm_body(const float* __restrict__ A,
                                              const float* __restrict__ B,
                                              float* __restrict__ C,
                                              int N, int K) {
    extern __shared__ char dynsmem[];
    uint32_t sbase = (smem_u32(dynsmem) + 1023) & ~1023u;

    const int tid  = threadIdx.x;
    const int warp = tid >> 5, lane = tid & 31;
    const int m0 = blockIdx.y * 128, n0 = blockIdx.x * 128;
    const int wm = (warp & 1) * 64, wn = (warp >> 1) * 32;
    const int NITER = K >> 5;

    const int lrow = tid >> 3, lc4 = tid & 7;
    uint32_t dst_off[4];
    const float* aptr[4];
    const float* bptr[4];
    #pragma unroll
    for (int i = 0; i < 4; i++) {
        int r = lrow + i * 32;
        dst_off[i] = sw128((uint32_t)(r * 128 + lc4 * 16));
        aptr[i] = A + (size_t)(m0 + r) * K + lc4 * 4;
        bptr[i] = B + (size_t)(n0 + r) * K + lc4 * 4;
    }

    auto issue = [&](int kc, int st) {
        uint32_t sa = sbase + st * STG_BYTES;
        uint32_t sb = sa + 16384;
        int koff = kc * 32;
        #pragma unroll
        for (int i = 0; i < 4; i++) {
            cp16(sa + dst_off[i], aptr[i] + koff);
            cp16(sb + dst_off[i], bptr[i] + koff);
        }
        CP_COMMIT();
    };

    float acc[4][4][4];
    #pragma unroll
    for (int i = 0; i < 4; i++)
        #pragma unroll
        for (int j = 0; j < 4; j++)
            #pragma unroll
            for (int k = 0; k < 4; k++) acc[i][j][k] = 0.f;

    issue(0, 0); issue(1, 1);

    const int mq   = lane >> 3;
    const int arow = (lane & 7) + ((mq & 1) << 3);
    const int aoff = (mq & 2) ? 16 : 0;
    const int brow = (lane & 7) + ((mq & 2) << 2);
    const int boff = (mq & 1) * 16;
    int arbase[4], arx[4];
    #pragma unroll
    for (int mt = 0; mt < 4; mt++) {
        int r = wm + mt*16 + arow;
        arbase[mt] = r * 128; arx[mt] = (r & 7) << 4;
    }
    int brbase[2], brx[2];
    #pragma unroll
    for (int np = 0; np < 2; np++) {
        int r = wn + np*16 + brow;
        brbase[np] = r * 128; brx[np] = (r & 7) << 4;
    }

    int rstage = 0, wstage = 2;
    for (int kc = 0; kc < NITER; kc++) {
        CP_WAIT1();
        __syncthreads();
        if (kc + 2 < NITER) issue(kc + 2, wstage);
        else CP_COMMIT();

        uint32_t sa = sbase + rstage * STG_BYTES;
        uint32_t sb = sa + 16384;
        rstage = (rstage == GST-1) ? 0 : rstage + 1;
        wstage = (wstage == GST-1) ? 0 : wstage + 1;

        #pragma unroll
        for (int ks = 0; ks < 4; ks++) {
            int kb = ks * 32;
            uint32_t af[4][4];
            #pragma unroll
            for (int mt = 0; mt < 4; mt++) {
                uint32_t addr = sa + arbase[mt] + (uint32_t)((kb + aoff) ^ arx[mt]);
                ldsm4(af[mt][0], af[mt][1], af[mt][2], af[mt][3], addr);
            }
            uint32_t bf[4][2];
            #pragma unroll
            for (int np = 0; np < 2; np++) {
                uint32_t addr = sb + brbase[np] + (uint32_t)((kb + boff) ^ brx[np]);
                ldsm4(bf[2*np][0], bf[2*np][1], bf[2*np+1][0], bf[2*np+1][1], addr);
            }
            #pragma unroll
            for (int mt = 0; mt < 4; mt++)
                #pragma unroll
                for (int nt = 0; nt < 4; nt++) {
                    asm volatile(
                        "mma.sync.aligned.m16n8k8.row.col.f32.tf32.tf32.f32 "
                        "{%0,%1,%2,%3}, {%4,%5,%6,%7}, {%8,%9}, {%0,%1,%2,%3};"
                        : "+f"(acc[mt][nt][0]), "+f"(acc[mt][nt][1]),
                          "+f"(acc[mt][nt][2]), "+f"(acc[mt][nt][3])
                        : "r"(af[mt][0]), "r"(af[mt][1]), "r"(af[mt][2]), "r"(af[mt][3]),
                          "r"(bf[nt][0]), "r"(bf[nt][1]));
                }
        }
    }

    #pragma unroll
    for (int mt = 0; mt < 4; mt++) {
        #pragma unroll
        for (int nt = 0; nt < 4; nt++) {
            int r = m0 + wm + mt*16 + (lane >> 2);
            int c = n0 + wn + nt*8 + 2*(lane & 3);
            *(float2*)&C[(size_t)r * N + c]       = make_float2(acc[mt][nt][0], acc[mt][nt][1]);
            *(float2*)&C[(size_t)(r + 8) * N + c] = make_float2(acc[mt][nt][2], acc[mt][nt][3]);
        }
    }
}

__global__ void __launch_bounds__(256, 2) mma_gemm1_kernel() {
    mma_gemm_body(g_h, g_w1t, g_zx, DIPP, DM);
}
__global__ void __launch_bounds__(256, 2) mma_gemm2_kernel() {
    mma_gemm_body(g_comb, g_w2t, g_o, DM, DI);
}

// ---------------- causal depthwise conv + silu + split + dt/dA ---------------
__global__ void conv_kernel(const float* __restrict__ cw_f, const float* __restrict__ cb_f,
                            const float* __restrict__ cw_r, const float* __restrict__ cb_r,
                            const float* __restrict__ dtb_f, const float* __restrict__ Al_f,
                            const float* __restrict__ dtb_r, const float* __restrict__ Al_r) {
    int t   = blockIdx.x;
    int dir = blockIdx.y;
    int b = t / LSEQ, lp = t % LSEQ;
    const float4* cw4 = (const float4*)(dir ? cw_r : cw_f);
    const float4* cb4 = (const float4*)(dir ? cb_r : cb_f);

    int rows[4];
    #pragma unroll
    for (int k = 0; k < 4; k++) {
        int j = lp + k - 3;
        rows[k] = (j >= 0) ? (b*LSEQ + (dir ? g_pos[b*LSEQ + j] : j)) : -1;
    }

    for (int c4 = threadIdx.x; c4 < CDIM/4; c4 += blockDim.x) {
        float4 bias = cb4[c4];
        float acc[4] = {bias.x, bias.y, bias.z, bias.w};
        float4 w[4];
        #pragma unroll
        for (int j = 0; j < 4; j++) w[j] = cw4[c4*4 + j];
        #pragma unroll
        for (int k = 0; k < 4; k++) {
            if (rows[k] >= 0) {
                float4 xv = *(const float4*)(g_zx + (size_t)rows[k]*DIPP + DI + c4*4);
                acc[0] = fmaf(((const float*)&w[0])[k], xv.x, acc[0]);
                acc[1] = fmaf(((const float*)&w[1])[k], xv.y, acc[1]);
                acc[2] = fmaf(((const float*)&w[2])[k], xv.z, acc[2]);
                acc[3] = fmaf(((const float*)&w[3])[k], xv.w, acc[3]);
            }
        }
        float4 v = make_float4(siluf(acc[0]), siluf(acc[1]), siluf(acc[2]), siluf(acc[3]));
        if (c4 < DI/4)                ((float4*)(g_xc[dir] + (size_t)t*DI))[c4] = v;
        else if (c4 < (DI+DS)/4)      ((float4*)(g_Bc[dir] + (size_t)t*DS))[c4 - DI/4] = v;
        else                          ((float4*)(g_Cc[dir] + (size_t)t*DS))[c4 - (DI+DS)/4] = v;
    }

    if (threadIdx.x < NH) {
        int hh = threadIdx.x;
        int srow = b*LSEQ + (dir ? g_pos[t] : lp);
        float dtr = g_zx[(size_t)srow*DIPP + DI + CDIM + hh] + (dir ? dtb_r : dtb_f)[hh];
        float dtv = (dtr > 20.f) ? dtr : log1pf(expf(dtr));
        float A = -expf((dir ? Al_r : Al_f)[hh]);
        g_dt[dir][(size_t)t*NH + hh] = dtv;
        g_dA[dir][(size_t)t*NH + hh] = expf(dtv * A);
    }
}

// ---------------- selective scan pass 1 (NCHUNK=2, double-buffered) -----------
// grid 512: bid = (bh<<2)|(ck<<1)|dir. 128 threads, thread owns 4p x 16n of h.
#define CH 16
#define NT (LCHUNK/CH)     // 32 tiles
__global__ void __launch_bounds__(128, 4) scan1_kernel(const float* __restrict__ Df,
                                                       const float* __restrict__ Dr) {
    int bid = blockIdx.x;
    int dir = bid & 1, ck = (bid >> 1) & 1, bh = bid >> 2;
    int b = bh / NH, hd = bh % NH;
    int tid = threadIdx.x;
    int lane = tid & 31, wd = tid >> 5;
    int nid = lane & 7, pg = lane >> 3;
    int p_base = wd*16 + pg*4;
    int n4 = nid*4;
    float Dv = (dir ? Dr : Df)[hd];
    const int t0 = ck * LCHUNK;

    __shared__ float sB[2][CH][DS], sC[2][CH][DS], sx[2][CH][HD];
    __shared__ float sdtf[2][CH], sdAf[2][CH];

    ull h2[4][8];
    #pragma unroll
    for (int p = 0; p < 4; p++)
        #pragma unroll
        for (int j = 0; j < 8; j++) h2[p][j] = 0ull;
    float cp = 1.f;

    const float* Bg  = g_Bc[dir] + (size_t)b*LSEQ*DS;
    const float* Cg  = g_Cc[dir] + (size_t)b*LSEQ*DS;
    const float* xg  = g_xc[dir] + (size_t)b*LSEQ*DI + (size_t)hd*HD;
    const float* dtg = g_dt[dir] + (size_t)b*LSEQ*NH + hd;
    const float* dAg = g_dA[dir] + (size_t)b*LSEQ*NH + hd;
    float* yg  = g_y[dir]  + (size_t)b*LSEQ*DI + (size_t)hd*HD;
    float* cpg = g_cp[dir] + (size_t)b*LSEQ*NH + hd;

    auto fill = [&](int tile, int buf) {
        int l0 = t0 + tile*CH;
        #pragma unroll
        for (int r = 0; r < 4; r++) {
            int e = r*128 + tid;
            int s = e >> 5, n = (e & 31) * 4;
            cp16(smem_u32(&sB[buf][s][n]), &Bg[(size_t)(l0+s)*DS + n]);
            cp16(smem_u32(&sC[buf][s][n]), &Cg[(size_t)(l0+s)*DS + n]);
        }
        #pragma unroll
        for (int r = 0; r < 2; r++) {
            int e = r*128 + tid;
            int s = e >> 4, p = (e & 15) * 4;
            cp16(smem_u32(&sx[buf][s][p]), &xg[(size_t)(l0+s)*DI + p]);
        }
        if (tid < CH) {
            cp4(smem_u32(&sdtf[buf][tid]), &dtg[(size_t)(l0+tid)*NH]);
            cp4(smem_u32(&sdAf[buf][tid]), &dAg[(size_t)(l0+tid)*NH]);
        }
        CP_COMMIT();
    };

    fill(0, 0);

    for (int tile = 0; tile < NT; tile++) {
        CP_WAIT0();
        __syncthreads();
        if (tile + 1 < NT) fill(tile + 1, (tile + 1) & 1);
        int buf = tile & 1;
        int l0 = t0 + tile*CH;

        #pragma unroll
        for (int s = 0; s < CH; s++) {
            float dt = sdtf[buf][s];
            float da = sdAf[buf][s];
            ull dA2 = pack2(da, da);
            float4 xv = *(const float4*)&sx[buf][s][p_base];
            ull kf2[4];
            {
                float k0 = dt*xv.x, k1 = dt*xv.y, k2 = dt*xv.z, k3 = dt*xv.w;
                kf2[0] = pack2(k0, k0); kf2[1] = pack2(k1, k1);
                kf2[2] = pack2(k2, k2); kf2[3] = pack2(k3, k3);
            }

            ull y2[4] = {0ull, 0ull, 0ull, 0ull};
            #pragma unroll
            for (int q = 0; q < 4; q++) {
                ulonglong2 bq = *(const ulonglong2*)&sB[buf][s][n4 + 32*q];
                ulonglong2 cq = *(const ulonglong2*)&sC[buf][s][n4 + 32*q];
                #pragma unroll
                for (int p = 0; p < 4; p++) {
                    ull t0v = mul2(h2[p][2*q], dA2);
                    fma2(h2[p][2*q], bq.x, kf2[p], t0v);
                    fma2(y2[p], h2[p][2*q], cq.x, y2[p]);
                    ull t1v = mul2(h2[p][2*q+1], dA2);
                    fma2(h2[p][2*q+1], bq.y, kf2[p], t1v);
                    fma2(y2[p], h2[p][2*q+1], cq.y, y2[p]);
                }
            }

            cp *= da;
            if (ck && tid == 0)
                cpg[(size_t)(l0+s)*NH] = cp;

            float yout[4];
            #pragma unroll
            for (int p = 0; p < 4; p++) {
                float a, c; unpack2(a, c, y2[p]);
                float yp = a + c;
                yp += __shfl_xor_sync(0xffffffffu, yp, 1);
                yp += __shfl_xor_sync(0xffffffffu, yp, 2);
                yp += __shfl_xor_sync(0xffffffffu, yp, 4);
                yout[p] = fmaf(Dv, ((const float*)&xv)[p], yp);
            }
            if (nid == 0)
                *(float4*)&yg[(size_t)(l0+s)*DI + p_base] =
                    make_float4(yout[0], yout[1], yout[2], yout[3]);
        }
    }

    if (ck == 0) {
        float* E = g_E + ((size_t)(dir*BSZ*NH + bh)) * (HD*DS);
        #pragma unroll
        for (int p = 0; p < 4; p++) {
            #pragma unroll
            for (int q = 0; q < 4; q++) {
                float a0, b0, a1, b1;
                unpack2(a0, b0, h2[p][2*q]);
                unpack2(a1, b1, h2[p][2*q+1]);
                *(float4*)&E[(size_t)(p_base+p)*DS + n4 + 32*q] =
                    make_float4(a0, b0, a1, b1);
            }
        }
    }
}

// ---------------- selective scan pass 3 (chunk-1 correction) ------------------
__global__ void __launch_bounds__(128) scan3_kernel() {
    int bid = blockIdx.x;
    int dir = bid & 1, th = (bid >> 1) & 1, bh = bid >> 2;
    int b = bh / NH, hd = bh % NH;
    int tid = threadIdx.x;
    int lane = tid & 31, wd = tid >> 5;
    int nid = lane & 7, pg = lane >> 3;
    int p_base = wd*16 + pg*4;
    int n4 = nid*4;

    const float* E = g_E + ((size_t)(dir*BSZ*NH + bh)) * (HD*DS);
    ull e2[4][8];
    #pragma unroll
    for (int p = 0; p < 4; p++)
        #pragma unroll
        for (int q = 0; q < 4; q++) {
            float4 v = *(const float4*)&E[(size_t)(p_base+p)*DS + n4 + 32*q];
            e2[p][2*q]   = pack2(v.x, v.y);
            e2[p][2*q+1] = pack2(v.z, v.w);
        }

    __shared__ float sC[CH][DS];
    __shared__ float scp[CH];

    const float* Cg  = g_Cc[dir] + (size_t)b*LSEQ*DS;
    const float* cpg = g_cp[dir] + (size_t)b*LSEQ*NH + hd;
    float* yg = g_y[dir] + (size_t)b*LSEQ*DI + (size_t)hd*HD;

    const int tstart = LCHUNK + th * 256;
    for (int l0 = tstart; l0 < tstart + 256; l0 += CH) {
        #pragma unroll
        for (int r = 0; r < 4; r++) {
            int e = r*128 + tid;
            int s = e >> 5, n = (e & 31) * 4;
            *(float4*)&sC[s][n] = *(const float4*)&Cg[(size_t)(l0+s)*DS + n];
        }
        if (tid < CH)
            scp[tid] = cpg[(size_t)(l0+tid)*NH];
        __syncthreads();

        #pragma unroll
        for (int s = 0; s < CH; s++) {
            ull y2[4] = {0ull, 0ull, 0ull, 0ull};
            #pragma unroll
            for (int q = 0; q < 4; q++) {
                ulonglong2 cq = *(const ulonglong2*)&sC[s][n4 + 32*q];
                #pragma unroll
                for (int p = 0; p < 4; p++) {
                    fma2(y2[p], e2[p][2*q],   cq.x, y2[p]);
                    fma2(y2[p], e2[p][2*q+1], cq.y, y2[p]);
                }
            }
            float cp = scp[s];
            float yout[4];
            #pragma unroll
            for (int p = 0; p < 4; p++) {
                float a, c; unpack2(a, c, y2[p]);
                float yp = a + c;
                yp += __shfl_xor_sync(0xffffffffu, yp, 1);
                yp += __shfl_xor_sync(0xffffffffu, yp, 2);
                yp += __shfl_xor_sync(0xffffffffu, yp, 4);
                yout[p] = cp * yp;
            }
            if (nid == 0) {
                float4 old = *(float4*)&yg[(size_t)(l0+s)*DI + p_base];
                old.x += yout[0]; old.y += yout[1];
                old.z += yout[2]; old.w += yout[3];
                *(float4*)&yg[(size_t)(l0+s)*DI + p_base] = old;
            }
        }
        __syncthreads();
    }
}

// ---------------- fused gate + RMSNorm + combine (R13-proven, 23us win) -------
// pos is an involution, so dir-1's row at output token t is rt=pos[t] and both
// directions gate from the SAME z row t. Writes g_comb directly.
__global__ void __launch_bounds__(256) gate_combine_kernel(const float* __restrict__ nwf,
                                                           const float* __restrict__ nwr) {
    int t = blockIdx.x;
    int b = t / LSEQ;
    int rt = b*LSEQ + g_pos[t];
    const float* y0 = g_y[0] + (size_t)t*DI;
    const float* y1 = g_y[1] + (size_t)rt*DI;
    const float* z  = g_zx + (size_t)t*DIPP;
    float* o = g_comb + (size_t)t*DI;

    float g0[8], g1[8];
    float s0 = 0.f, s1 = 0.f;
    #pragma unroll
    for (int r = 0; r < 8; r++) {
        int c = r*256 + threadIdx.x;
        float sil = siluf(z[c]);
        float a = y0[c] * sil;
        float d = y1[c] * sil;
        g0[r] = a; g1[r] = d;
        s0 = fmaf(a, a, s0);
        s1 = fmaf(d, d, s1);
    }
    float tot0 = block_sum(s0);
    float tot1 = block_sum(s1);
    float rs0 = rsqrtf(tot0 / DI + EPSV);
    float rs1 = rsqrtf(tot1 / DI + EPSV);
    #pragma unroll
    for (int r = 0; r < 8; r++) {
        int c = r*256 + threadIdx.x;
        o[c] = rna_tf32(0.5f * (g0[r]*rs0*nwf[c] + g1[r]*rs1*nwr[c]));
    }
}

// ---------------- launch -------------------------------------------------------
extern "C" void kernel_launch(void* const* d_in, const int* in_sizes, int n_in,
                              void* d_out, int out_size) {
    const float* hidden  = (const float*)d_in[0];
    const unsigned char* mask = (const unsigned char*)d_in[1];
    const float* in_proj = (const float*)d_in[2];
    const float* out_proj= (const float*)d_in[3];
    const float* cw_f  = (const float*)d_in[4];
    const float* cb_f  = (const float*)d_in[5];
    const float* dtb_f = (const float*)d_in[6];
    const float* Al_f  = (const float*)d_in[7];
    const float* D_f   = (const float*)d_in[8];
    const float* nw_f  = (const float*)d_in[9];
    const float* cw_r  = (const float*)d_in[10];
    const float* cb_r  = (const float*)d_in[11];
    const float* dtb_r = (const float*)d_in[12];
    const float* Al_r  = (const float*)d_in[13];
    const float* D_r   = (const float*)d_in[14];
    const float* nw_r  = (const float*)d_in[15];
    float* out = (float*)d_out;

    cudaFuncSetAttribute(mma_gemm1_kernel, cudaFuncAttributeMaxDynamicSharedMemorySize, GEMM_SMEM);
    cudaFuncSetAttribute(mma_gemm2_kernel, cudaFuncAttributeMaxDynamicSharedMemorySize, GEMM_SMEM);

    // scan1 at launch index 3 for ncu capture
    fused_pre_kernel<<<W1B + BSZ + TOK, 256>>>(hidden, mask, in_proj);
    mma_gemm1_kernel<<<dim3(DIPP/128, TOK/128), 256, GEMM_SMEM>>>();
    conv_kernel<<<dim3(TOK, 2), 256>>>(cw_f, cb_f, cw_r, cb_r, dtb_f, Al_f, dtb_r, Al_r);
    scan1_kernel<<<BSZ*NH*4, 128>>>(D_f, D_r);
    scan3_kernel<<<BSZ*NH*4, 128>>>();
    gate_combine_kernel<<<TOK, 256>>>(nw_f, nw_r);
    prep_w2_kernel<<<W2B, 256>>>(out_proj);
    mma_gemm2_kernel<<<dim3(DM/128, TOK/128), 256, GEMM_SMEM>>>();
    ln_out_kernel<<<TOK, 256>>>(out);
}